// round 14
// baseline (speedup 1.0000x reference)
#include <cuda_runtime.h>

#define NN   100000
#define NE   1600000
#define FIN  128
#define HID  64
#define NCLS 40

// ---- scratch (device globals; ONLY referenced inside device code) ----
__device__ __align__(16) float g_h   [NN * HID];   // GEMM output, pre-scaled by dinv[row]
__device__ __align__(16) float g_out [NN * HID];   // aggregated output (width 64)
__device__ float g_dinv[NN];
__device__ int   g_cnt [NN];          // in-degree (excl self-loop)
__device__ int   g_cur [NN];          // fill cursors
__device__ int   g_off [NN + 1];      // CSR offsets
__device__ int   g_csr [NE];          // src only, grouped by dst
__device__ int   g_is64;              // edge-index dtype probe

__device__ __forceinline__ int edge_at(const void* eiv, int idx) {
    long long v = g_is64 ? ((const long long*)eiv)[idx] : (long long)((const int*)eiv)[idx];
    return (v < 0) ? 0 : (v >= NN ? NN - 1 : (int)v);
}

// ------------------------------------------------------------------
// prep: zero counters everywhere; block 0 additionally runs the
// edge-dtype probe (int64 values < 2^31 => all odd 32-bit words 0).
// ------------------------------------------------------------------
__global__ void k_prep(const unsigned int* __restrict__ w) {
    int i = blockIdx.x * blockDim.x + threadIdx.x;
    if (i < NN) { g_cnt[i] = 0; g_cur[i] = 0; }
    if (blockIdx.x == 0) {
        __shared__ int nz;
        if (threadIdx.x == 0) nz = 0;
        __syncthreads();
        int found = 0;
        for (int k = 1 + threadIdx.x * 128; k < 2 * NE; k += 256 * 128)
            if (w[k] != 0u) found = 1;
        if (found) atomicOr(&nz, 1);
        __syncthreads();
        if (threadIdx.x == 0) g_is64 = (nz == 0) ? 1 : 0;
    }
}

__global__ void k_hist(const void* __restrict__ eiv) {
    int e = blockIdx.x * blockDim.x + threadIdx.x;
    if (e >= NE) return;
    atomicAdd(&g_cnt[edge_at(eiv, NE + e)], 1);
}

// ------------------------------------------------------------------
// scan (+dinv fused): offsets from g_cnt; dinv = rsqrt(deg+1).
// ------------------------------------------------------------------
#define SCAN_T 1024
__global__ void k_scan() {
    int t = threadIdx.x;
    const int chunk = (NN + SCAN_T - 1) / SCAN_T;
    int start = t * chunk;
    int end = start + chunk; if (end > NN) end = NN;
    int s = 0;
    for (int i = start; i < end; i++) {
        int c = g_cnt[i];
        g_off[i] = s; s += c;
        g_dinv[i] = rsqrtf((float)(c + 1));
    }
    __shared__ int sums[SCAN_T];
    sums[t] = s;
    __syncthreads();
    for (int o = 1; o < SCAN_T; o <<= 1) {
        int v = (t >= o) ? sums[t - o] : 0;
        __syncthreads();
        sums[t] += v;
        __syncthreads();
    }
    int base = (t == 0) ? 0 : sums[t - 1];
    for (int i = start; i < end; i++) g_off[i] += base;
    if (t == SCAN_T - 1) g_off[NN] = sums[SCAN_T - 1];
}

// ------------------------------------------------------------------
// GEMM body: g_h[n,F] = dinv[n] * act(Xsrc[n,K]) @ W[K,F]
// ------------------------------------------------------------------
template <int K, int F, int RF, int RM, bool HASB, bool FROMG>
__device__ __forceinline__ void gemm_body(const float* __restrict__ X,
                                          const float* __restrict__ W,
                                          const float* __restrict__ bin,
                                          int bid) {
    constexpr int NF = F / RF;
    constexpr int MT = 256 / NF;
    constexpr int TM = MT * RM;

    const float4* __restrict__ X4 =
        FROMG ? (const float4*)g_out : (const float4*)X;

    __shared__ float Ws[K * F];
    __shared__ float Bs[K];

    int tid = threadIdx.x;
    for (int i = tid; i < K * F; i += 256) Ws[i] = W[i];
    if (HASB) for (int i = tid; i < K; i += 256) Bs[i] = bin[i];
    __syncthreads();

    int fth  = tid % NF;
    int mth  = tid / NF;
    int f0   = fth * RF;
    int row0 = bid * TM + mth * RM;

    float acc[RM][RF];
#pragma unroll
    for (int m = 0; m < RM; m++)
#pragma unroll
        for (int j = 0; j < RF; j++) acc[m][j] = 0.f;

#pragma unroll
    for (int k4 = 0; k4 < K; k4 += 4) {
        float xr[RM][4];
#pragma unroll
        for (int m = 0; m < RM; m++) {
            int r = row0 + m;
            float4 v = (r < NN) ? X4[(r * K + k4) >> 2]
                                : make_float4(0.f, 0.f, 0.f, 0.f);
            if (HASB) {
                v.x = fmaxf(v.x + Bs[k4 + 0], 0.f);
                v.y = fmaxf(v.y + Bs[k4 + 1], 0.f);
                v.z = fmaxf(v.z + Bs[k4 + 2], 0.f);
                v.w = fmaxf(v.w + Bs[k4 + 3], 0.f);
            }
            xr[m][0] = v.x; xr[m][1] = v.y; xr[m][2] = v.z; xr[m][3] = v.w;
        }
#pragma unroll
        for (int kk = 0; kk < 4; kk++) {
#pragma unroll
            for (int j = 0; j < RF; j++) {
                float wv = Ws[(k4 + kk) * F + f0 + j];
#pragma unroll
                for (int m = 0; m < RM; m++)
                    acc[m][j] = fmaf(xr[m][kk], wv, acc[m][j]);
            }
        }
    }

#pragma unroll
    for (int m = 0; m < RM; m++) {
        int r = row0 + m;
        if (r < NN) {
            float di = g_dinv[r];
#pragma unroll
            for (int j = 0; j < RF; j++)
                g_h[r * F + f0 + j] = acc[m][j] * di;
        }
    }
}

template <int K, int F, int RF, int RM, bool HASB, bool FROMG>
__global__ void k_gemm(const float* __restrict__ X,
                       const float* __restrict__ W,
                       const float* __restrict__ bin) {
    gemm_body<K, F, RF, RM, HASB, FROMG>(X, W, bin, blockIdx.x);
}

// ------------------------------------------------------------------
// Fused: blocks [0, G1) run layer-1 GEMM; blocks [G1, G1+GF) run CSR
// fill. Independent outputs (g_h vs g_csr/g_cur); both ready post-scan.
// ------------------------------------------------------------------
#define G1 ((NN + 63) / 64)          // layer-1 GEMM blocks (TM = 64)
#define GF ((NE + 255) / 256)        // fill blocks

__global__ void k_fill_gemm1(const float* __restrict__ X,
                             const float* __restrict__ W1,
                             const void* __restrict__ eiv) {
    if (blockIdx.x < G1) {
        gemm_body<FIN, HID, 4, 4, false, false>(X, W1, W1, blockIdx.x);
    } else {
        int e = (blockIdx.x - G1) * 256 + threadIdx.x;
        if (e >= NE) return;
        int s = edge_at(eiv, e);
        int d = edge_at(eiv, NE + e);
        int idx = g_off[d] + atomicAdd(&g_cur[d], 1);
        g_csr[idx] = s;
    }
}

// ------------------------------------------------------------------
// Aggregation F=64: warp per dst node; ONE coalesced load grabs up to
// 32 edge indices, broadcast via shfl; row loads 8-deep independent.
// out[dst] = dinv[dst] * (h'[dst] + sum h'[src])
// ------------------------------------------------------------------
__global__ void k_agg64() {
    int gw   = (blockIdx.x * blockDim.x + threadIdx.x) >> 5;
    int lane = threadIdx.x & 31;
    if (gw >= NN) return;

    const float2* __restrict__ h2 = (const float2*)g_h;   // row = 32 float2

    float2 a = h2[gw * 32 + lane];    // self term (h' has dinv folded)

    int b = g_off[gw], e = g_off[gw + 1];
    for (int base = b; base < e; base += 32) {
        int n = e - base; if (n > 32) n = 32;
        int idx = (lane < n) ? g_csr[base + lane] : 0;   // coalesced
        int j = 0;
        for (; j + 8 <= n; j += 8) {
            int s0 = __shfl_sync(0xFFFFFFFFu, idx, j);
            int s1 = __shfl_sync(0xFFFFFFFFu, idx, j + 1);
            int s2 = __shfl_sync(0xFFFFFFFFu, idx, j + 2);
            int s3 = __shfl_sync(0xFFFFFFFFu, idx, j + 3);
            int s4 = __shfl_sync(0xFFFFFFFFu, idx, j + 4);
            int s5 = __shfl_sync(0xFFFFFFFFu, idx, j + 5);
            int s6 = __shfl_sync(0xFFFFFFFFu, idx, j + 6);
            int s7 = __shfl_sync(0xFFFFFFFFu, idx, j + 7);
            float2 r0 = h2[s0 * 32 + lane];
            float2 r1 = h2[s1 * 32 + lane];
            float2 r2 = h2[s2 * 32 + lane];
            float2 r3 = h2[s3 * 32 + lane];
            float2 r4 = h2[s4 * 32 + lane];
            float2 r5 = h2[s5 * 32 + lane];
            float2 r6 = h2[s6 * 32 + lane];
            float2 r7 = h2[s7 * 32 + lane];
            a.x += (r0.x + r1.x) + (r2.x + r3.x) + (r4.x + r5.x) + (r6.x + r7.x);
            a.y += (r0.y + r1.y) + (r2.y + r3.y) + (r4.y + r5.y) + (r6.y + r7.y);
        }
        for (; j < n; j++) {
            int s = __shfl_sync(0xFFFFFFFFu, idx, j);
            float2 r = h2[s * 32 + lane];
            a.x += r.x; a.y += r.y;
        }
    }

    float di = g_dinv[gw];
    a.x *= di; a.y *= di;
    ((float2*)g_out)[gw * 32 + lane] = a;
}

// ------------------------------------------------------------------
// Layer-3 aggregation (F=40, 20 float2 lanes) fused with
// bias+relu+log_softmax. Same broadcast-index scheme.
// ------------------------------------------------------------------
__global__ void k_agg40_lsm(const float* __restrict__ b3, float* __restrict__ out) {
    int gw   = (blockIdx.x * blockDim.x + threadIdx.x) >> 5;
    int lane = threadIdx.x & 31;
    if (gw >= NN) return;

    const float2* __restrict__ h2 = (const float2*)g_h;   // row = 20 float2
    bool act = lane < 20;
    int  sl  = act ? lane : 0;

    float2 a = act ? h2[gw * 20 + sl] : make_float2(0.f, 0.f);

    int b = g_off[gw], e = g_off[gw + 1];
    for (int base = b; base < e; base += 32) {
        int n = e - base; if (n > 32) n = 32;
        int idx = (lane < n) ? g_csr[base + lane] : 0;
        int j = 0;
        for (; j + 8 <= n; j += 8) {
            int s0 = __shfl_sync(0xFFFFFFFFu, idx, j);
            int s1 = __shfl_sync(0xFFFFFFFFu, idx, j + 1);
            int s2 = __shfl_sync(0xFFFFFFFFu, idx, j + 2);
            int s3 = __shfl_sync(0xFFFFFFFFu, idx, j + 3);
            int s4 = __shfl_sync(0xFFFFFFFFu, idx, j + 4);
            int s5 = __shfl_sync(0xFFFFFFFFu, idx, j + 5);
            int s6 = __shfl_sync(0xFFFFFFFFu, idx, j + 6);
            int s7 = __shfl_sync(0xFFFFFFFFu, idx, j + 7);
            if (act) {
                float2 r0 = h2[s0 * 20 + sl];
                float2 r1 = h2[s1 * 20 + sl];
                float2 r2 = h2[s2 * 20 + sl];
                float2 r3 = h2[s3 * 20 + sl];
                float2 r4 = h2[s4 * 20 + sl];
                float2 r5 = h2[s5 * 20 + sl];
                float2 r6 = h2[s6 * 20 + sl];
                float2 r7 = h2[s7 * 20 + sl];
                a.x += (r0.x + r1.x) + (r2.x + r3.x) + (r4.x + r5.x) + (r6.x + r7.x);
                a.y += (r0.y + r1.y) + (r2.y + r3.y) + (r4.y + r5.y) + (r6.y + r7.y);
            }
        }
        for (; j < n; j++) {
            int s = __shfl_sync(0xFFFFFFFFu, idx, j);
            if (act) {
                float2 r = h2[s * 20 + sl];
                a.x += r.x; a.y += r.y;
            }
        }
    }

    // dinv scale + bias + relu (two classes per active lane)
    float v0 = -1e30f, v1 = -1e30f;
    if (act) {
        float di = g_dinv[gw];
        float2 bb = ((const float2*)b3)[sl];
        v0 = fmaxf(a.x * di + bb.x, 0.f);
        v1 = fmaxf(a.y * di + bb.y, 0.f);
    }

    // log_softmax over 40 values spread across 20 lanes x 2
    float m = fmaxf(v0, v1);
#pragma unroll
    for (int o = 16; o > 0; o >>= 1)
        m = fmaxf(m, __shfl_xor_sync(0xFFFFFFFFu, m, o));

    float s = act ? (__expf(v0 - m) + __expf(v1 - m)) : 0.f;
#pragma unroll
    for (int o = 16; o > 0; o >>= 1)
        s += __shfl_xor_sync(0xFFFFFFFFu, s, o);

    float lse = m + __logf(s);
    if (act) {
        float2 r = make_float2(v0 - lse, v1 - lse);
        ((float2*)out)[gw * 20 + sl] = r;
    }
}

extern "C" void kernel_launch(void* const* d_in, const int* in_sizes, int n_in,
                              void* d_out, int out_size) {
    // ---- bind inputs BY ELEMENT COUNT (robust to metadata ordering) ----
    const float* x  = 0;
    const void*  ei = 0;
    const float *W1 = 0, *W2 = 0, *W3 = 0, *b1 = 0, *b2 = 0, *b3 = 0;
    for (int i = 0; i < n_in; i++) {
        long long sz = in_sizes[i];
        const void* p = d_in[i];
        if      (sz == (long long)NN * FIN)  x  = (const float*)p;
        else if (sz == 2LL * NE)             ei = p;
        else if (sz == FIN * HID)            W1 = (const float*)p;
        else if (sz == HID * HID)            W2 = (const float*)p;
        else if (sz == HID * NCLS)           W3 = (const float*)p;
        else if (sz == NCLS)                 b3 = (const float*)p;
        else if (sz == HID) {
            if (!b1) b1 = (const float*)p; else b2 = (const float*)p;
        }
    }
    float* out = (float*)d_out;
    if (!x || !ei || !W1 || !W2 || !W3 || !b1 || !b2 || !b3) return;

    const int TB = 256;
    int gN = (NN + TB - 1) / TB;
    int gE = (NE + TB - 1) / TB;
    int gW = (NN * 32 + TB - 1) / TB;   // warp-per-node grids

    // 0: zero + dtype probe
    k_prep<<<gN, TB>>>((const unsigned int*)ei);
    // 1: degree histogram
    k_hist<<<gE, TB>>>(ei);
    // 2: scan + dinv
    k_scan<<<1, SCAN_T>>>();
    // 3: CSR fill || layer-1 GEMM (128->64)   [profiled launch]
    k_fill_gemm1<<<G1 + GF, TB>>>(x, W1, ei);
    // 4: layer-1 aggregation
    k_agg64<<<gW, TB>>>();
    // 5: layer-2 GEMM (64->64, relu(prev+b1) fused)
    k_gemm<HID, HID, 4, 4, true, true><<<(NN + 63) / 64, TB>>>(x, W2, b1);
    // 6: layer-2 aggregation
    k_agg64<<<gW, TB>>>();
    // 7: layer-3 GEMM (64->40, relu(prev+b2) fused)
    k_gemm<HID, NCLS, 5, 4, true, true><<<(NN + 127) / 128, TB>>>(x, W3, b2);
    // 8: layer-3 aggregation + bias + relu + log_softmax
    k_agg40_lsm<<<gW, TB>>>(b3, out);
}

// round 15
// speedup vs baseline: 1.0367x; 1.0367x over previous
#include <cuda_runtime.h>

#define NN   100000
#define NE   1600000
#define FIN  128
#define HID  64
#define NCLS 40

// ---- scratch (device globals; ONLY referenced inside device code) ----
__device__ __align__(16) float g_h   [NN * HID];   // GEMM output, pre-scaled by dinv[row]
__device__ __align__(16) float g_out [NN * HID];   // aggregated output (width 64)
__device__ float g_dinv[NN];
__device__ int   g_cnt [NN];          // in-degree (excl self-loop)
__device__ int   g_cur [NN];          // fill cursors
__device__ int   g_off [NN + 1];      // CSR offsets
__device__ int   g_csr [NE];          // src only, grouped by dst
__device__ int   g_is64;              // edge-index dtype probe

__device__ __forceinline__ int edge_at(const void* eiv, int idx) {
    long long v = g_is64 ? ((const long long*)eiv)[idx] : (long long)((const int*)eiv)[idx];
    return (v < 0) ? 0 : (v >= NN ? NN - 1 : (int)v);
}

// ------------------------------------------------------------------
// prep: zero counters; block 0 also runs the edge-dtype probe.
// ------------------------------------------------------------------
__global__ void k_prep(const unsigned int* __restrict__ w) {
    int i = blockIdx.x * blockDim.x + threadIdx.x;
    if (i < NN) { g_cnt[i] = 0; g_cur[i] = 0; }
    if (blockIdx.x == 0) {
        __shared__ int nz;
        if (threadIdx.x == 0) nz = 0;
        __syncthreads();
        int found = 0;
        for (int k = 1 + threadIdx.x * 128; k < 2 * NE; k += 256 * 128)
            if (w[k] != 0u) found = 1;
        if (found) atomicOr(&nz, 1);
        __syncthreads();
        if (threadIdx.x == 0) g_is64 = (nz == 0) ? 1 : 0;
    }
}

__global__ void k_hist(const void* __restrict__ eiv) {
    int e = blockIdx.x * blockDim.x + threadIdx.x;
    if (e >= NE) return;
    atomicAdd(&g_cnt[edge_at(eiv, NE + e)], 1);
}

// ------------------------------------------------------------------
// scan (+dinv fused)
// ------------------------------------------------------------------
#define SCAN_T 1024
__global__ void k_scan() {
    int t = threadIdx.x;
    const int chunk = (NN + SCAN_T - 1) / SCAN_T;
    int start = t * chunk;
    int end = start + chunk; if (end > NN) end = NN;
    int s = 0;
    for (int i = start; i < end; i++) {
        int c = g_cnt[i];
        g_off[i] = s; s += c;
        g_dinv[i] = rsqrtf((float)(c + 1));
    }
    __shared__ int sums[SCAN_T];
    sums[t] = s;
    __syncthreads();
    for (int o = 1; o < SCAN_T; o <<= 1) {
        int v = (t >= o) ? sums[t - o] : 0;
        __syncthreads();
        sums[t] += v;
        __syncthreads();
    }
    int base = (t == 0) ? 0 : sums[t - 1];
    for (int i = start; i < end; i++) g_off[i] += base;
    if (t == SCAN_T - 1) g_off[NN] = sums[SCAN_T - 1];
}

// ------------------------------------------------------------------
// GEMM body: g_h[n,F] = dinv[n] * act(Xsrc[n,K]) @ W[K,F]
// Weight reads use LDS.128 when RF==4 (f0 16B-aligned).
// ------------------------------------------------------------------
template <int K, int F, int RF, int RM, bool HASB, bool FROMG>
__device__ __forceinline__ void gemm_body(const float* __restrict__ X,
                                          const float* __restrict__ W,
                                          const float* __restrict__ bin,
                                          int bid) {
    constexpr int NF = F / RF;
    constexpr int MT = 256 / NF;
    constexpr int TM = MT * RM;

    const float4* __restrict__ X4 =
        FROMG ? (const float4*)g_out : (const float4*)X;

    __shared__ __align__(16) float Ws[K * F];
    __shared__ float Bs[K];

    int tid = threadIdx.x;
    for (int i = tid; i < K * F; i += 256) Ws[i] = W[i];
    if (HASB) for (int i = tid; i < K; i += 256) Bs[i] = bin[i];
    __syncthreads();

    int fth  = tid % NF;
    int mth  = tid / NF;
    int f0   = fth * RF;
    int row0 = bid * TM + mth * RM;

    float acc[RM][RF];
#pragma unroll
    for (int m = 0; m < RM; m++)
#pragma unroll
        for (int j = 0; j < RF; j++) acc[m][j] = 0.f;

#pragma unroll
    for (int k4 = 0; k4 < K; k4 += 4) {
        float xr[RM][4];
#pragma unroll
        for (int m = 0; m < RM; m++) {
            int r = row0 + m;
            float4 v = (r < NN) ? X4[(r * K + k4) >> 2]
                                : make_float4(0.f, 0.f, 0.f, 0.f);
            if (HASB) {
                v.x = fmaxf(v.x + Bs[k4 + 0], 0.f);
                v.y = fmaxf(v.y + Bs[k4 + 1], 0.f);
                v.z = fmaxf(v.z + Bs[k4 + 2], 0.f);
                v.w = fmaxf(v.w + Bs[k4 + 3], 0.f);
            }
            xr[m][0] = v.x; xr[m][1] = v.y; xr[m][2] = v.z; xr[m][3] = v.w;
        }
#pragma unroll
        for (int kk = 0; kk < 4; kk++) {
            float wv[RF];
            if (RF == 4) {
                float4 w4 = *reinterpret_cast<const float4*>(&Ws[(k4 + kk) * F + f0]);
                wv[0] = w4.x; wv[1] = w4.y; wv[2] = w4.z; wv[3] = w4.w;
            } else {
#pragma unroll
                for (int j = 0; j < RF; j++) wv[j] = Ws[(k4 + kk) * F + f0 + j];
            }
#pragma unroll
            for (int j = 0; j < RF; j++) {
#pragma unroll
                for (int m = 0; m < RM; m++)
                    acc[m][j] = fmaf(xr[m][kk], wv[j], acc[m][j]);
            }
        }
    }

#pragma unroll
    for (int m = 0; m < RM; m++) {
        int r = row0 + m;
        if (r < NN) {
            float di = g_dinv[r];
#pragma unroll
            for (int j = 0; j < RF; j++)
                g_h[r * F + f0 + j] = acc[m][j] * di;
        }
    }
}

template <int K, int F, int RF, int RM, bool HASB, bool FROMG>
__global__ void k_gemm(const float* __restrict__ X,
                       const float* __restrict__ W,
                       const float* __restrict__ bin) {
    gemm_body<K, F, RF, RM, HASB, FROMG>(X, W, bin, blockIdx.x);
}

// ------------------------------------------------------------------
// Fused: blocks [0, G1) run layer-1 GEMM; rest run CSR fill.
// ------------------------------------------------------------------
#define G1 ((NN + 63) / 64)          // layer-1 GEMM blocks (TM = 64)
#define GF ((NE + 255) / 256)        // fill blocks

__global__ void k_fill_gemm1(const float* __restrict__ X,
                             const float* __restrict__ W1,
                             const void* __restrict__ eiv) {
    if (blockIdx.x < G1) {
        gemm_body<FIN, HID, 4, 4, false, false>(X, W1, W1, blockIdx.x);
    } else {
        int e = (blockIdx.x - G1) * 256 + threadIdx.x;
        if (e >= NE) return;
        int s = edge_at(eiv, e);
        int d = edge_at(eiv, NE + e);
        int idx = g_off[d] + atomicAdd(&g_cur[d], 1);
        g_csr[idx] = s;
    }
}

// ------------------------------------------------------------------
// Aggregation F=64: warp per dst node, all 32 lanes on one row
// (float2), lane-uniform csr loads (HW broadcast), 8-deep batches.
// ------------------------------------------------------------------
__global__ void k_agg64() {
    int gw   = (blockIdx.x * blockDim.x + threadIdx.x) >> 5;
    int lane = threadIdx.x & 31;
    if (gw >= NN) return;

    const float2* __restrict__ h2 = (const float2*)g_h;   // row = 32 float2

    float2 a = h2[gw * 32 + lane];    // self term (h' has dinv folded)

    int b = g_off[gw], e = g_off[gw + 1];
    int i = b;
    for (; i + 8 <= e; i += 8) {
        int s0 = g_csr[i    ], s1 = g_csr[i + 1];
        int s2 = g_csr[i + 2], s3 = g_csr[i + 3];
        int s4 = g_csr[i + 4], s5 = g_csr[i + 5];
        int s6 = g_csr[i + 6], s7 = g_csr[i + 7];
        float2 r0 = h2[s0 * 32 + lane];
        float2 r1 = h2[s1 * 32 + lane];
        float2 r2 = h2[s2 * 32 + lane];
        float2 r3 = h2[s3 * 32 + lane];
        float2 r4 = h2[s4 * 32 + lane];
        float2 r5 = h2[s5 * 32 + lane];
        float2 r6 = h2[s6 * 32 + lane];
        float2 r7 = h2[s7 * 32 + lane];
        a.x += (r0.x + r1.x) + (r2.x + r3.x) + (r4.x + r5.x) + (r6.x + r7.x);
        a.y += (r0.y + r1.y) + (r2.y + r3.y) + (r4.y + r5.y) + (r6.y + r7.y);
    }
    for (; i < e; i++) {
        float2 r = h2[g_csr[i] * 32 + lane];
        a.x += r.x; a.y += r.y;
    }

    float di = g_dinv[gw];
    a.x *= di; a.y *= di;
    ((float2*)g_out)[gw * 32 + lane] = a;
}

// ------------------------------------------------------------------
// Layer-3 aggregation (F=40, 20 float2 lanes) fused with
// bias+relu+log_softmax.
// ------------------------------------------------------------------
__global__ void k_agg40_lsm(const float* __restrict__ b3, float* __restrict__ out) {
    int gw   = (blockIdx.x * blockDim.x + threadIdx.x) >> 5;
    int lane = threadIdx.x & 31;
    if (gw >= NN) return;

    const float2* __restrict__ h2 = (const float2*)g_h;   // row = 20 float2
    bool act = lane < 20;
    int  sl  = act ? lane : 0;

    float2 a = act ? h2[gw * 20 + sl] : make_float2(0.f, 0.f);

    int b = g_off[gw], e = g_off[gw + 1];
    int i = b;
    for (; i + 8 <= e; i += 8) {
        int s0 = g_csr[i    ], s1 = g_csr[i + 1];
        int s2 = g_csr[i + 2], s3 = g_csr[i + 3];
        int s4 = g_csr[i + 4], s5 = g_csr[i + 5];
        int s6 = g_csr[i + 6], s7 = g_csr[i + 7];
        if (act) {
            float2 r0 = h2[s0 * 20 + sl];
            float2 r1 = h2[s1 * 20 + sl];
            float2 r2 = h2[s2 * 20 + sl];
            float2 r3 = h2[s3 * 20 + sl];
            float2 r4 = h2[s4 * 20 + sl];
            float2 r5 = h2[s5 * 20 + sl];
            float2 r6 = h2[s6 * 20 + sl];
            float2 r7 = h2[s7 * 20 + sl];
            a.x += (r0.x + r1.x) + (r2.x + r3.x) + (r4.x + r5.x) + (r6.x + r7.x);
            a.y += (r0.y + r1.y) + (r2.y + r3.y) + (r4.y + r5.y) + (r6.y + r7.y);
        }
    }
    for (; i < e; i++) {
        if (act) {
            float2 r = h2[g_csr[i] * 20 + sl];
            a.x += r.x; a.y += r.y;
        }
    }

    // dinv scale + bias + relu (two classes per active lane)
    float v0 = -1e30f, v1 = -1e30f;
    if (act) {
        float di = g_dinv[gw];
        float2 bb = ((const float2*)b3)[sl];
        v0 = fmaxf(a.x * di + bb.x, 0.f);
        v1 = fmaxf(a.y * di + bb.y, 0.f);
    }

    // log_softmax over 40 values spread across 20 lanes x 2
    float m = fmaxf(v0, v1);
#pragma unroll
    for (int o = 16; o > 0; o >>= 1)
        m = fmaxf(m, __shfl_xor_sync(0xFFFFFFFFu, m, o));

    float s = act ? (__expf(v0 - m) + __expf(v1 - m)) : 0.f;
#pragma unroll
    for (int o = 16; o > 0; o >>= 1)
        s += __shfl_xor_sync(0xFFFFFFFFu, s, o);

    float lse = m + __logf(s);
    if (act) {
        float2 r = make_float2(v0 - lse, v1 - lse);
        ((float2*)out)[gw * 20 + sl] = r;
    }
}

extern "C" void kernel_launch(void* const* d_in, const int* in_sizes, int n_in,
                              void* d_out, int out_size) {
    // ---- bind inputs BY ELEMENT COUNT (robust to metadata ordering) ----
    const float* x  = 0;
    const void*  ei = 0;
    const float *W1 = 0, *W2 = 0, *W3 = 0, *b1 = 0, *b2 = 0, *b3 = 0;
    for (int i = 0; i < n_in; i++) {
        long long sz = in_sizes[i];
        const void* p = d_in[i];
        if      (sz == (long long)NN * FIN)  x  = (const float*)p;
        else if (sz == 2LL * NE)             ei = p;
        else if (sz == FIN * HID)            W1 = (const float*)p;
        else if (sz == HID * HID)            W2 = (const float*)p;
        else if (sz == HID * NCLS)           W3 = (const float*)p;
        else if (sz == NCLS)                 b3 = (const float*)p;
        else if (sz == HID) {
            if (!b1) b1 = (const float*)p; else b2 = (const float*)p;
        }
    }
    float* out = (float*)d_out;
    if (!x || !ei || !W1 || !W2 || !W3 || !b1 || !b2 || !b3) return;

    const int TB = 256;
    int gN = (NN + TB - 1) / TB;
    int gE = (NE + TB - 1) / TB;
    int gW = (NN * 32 + TB - 1) / TB;   // warp-per-node grids

    // 0: zero + dtype probe
    k_prep<<<gN, TB>>>((const unsigned int*)ei);
    // 1: degree histogram
    k_hist<<<gE, TB>>>(ei);
    // 2: scan + dinv
    k_scan<<<1, SCAN_T>>>();
    // 3: CSR fill || layer-1 GEMM (128->64)   [profiled launch]
    k_fill_gemm1<<<G1 + GF, TB>>>(x, W1, ei);
    // 4: layer-1 aggregation
    k_agg64<<<gW, TB>>>();
    // 5: layer-2 GEMM (64->64, relu(prev+b1) fused)
    k_gemm<HID, HID, 4, 4, true, true><<<(NN + 63) / 64, TB>>>(x, W2, b1);
    // 6: layer-2 aggregation
    k_agg64<<<gW, TB>>>();
    // 7: layer-3 GEMM (64->40, relu(prev+b2) fused)
    k_gemm<HID, NCLS, 5, 4, true, true><<<(NN + 127) / 128, TB>>>(x, W3, b2);
    // 8: layer-3 aggregation + bias + relu + log_softmax
    k_agg40_lsm<<<gW, TB>>>(b3, out);
}